// round 3
// baseline (speedup 1.0000x reference)
#include <cuda_runtime.h>
#include <math.h>

#define N_NODES 81
#define N_EDGES 1620
#define IN_DIM  10
#define HIDDEN  8192
#define ACTIONS 729

// ---------------- device scratch (no allocations allowed) ----------------
__device__ float g_xc[N_NODES * IN_DIM];       // (A_norm @ x)
__device__ float g_snorm[N_NODES * HIDDEN];    // per-node LN output (pre-affine)
__device__ float g_gvec[HIDDEN];               // pooled + affine vector
__device__ float g_acc1[HIDDEN];               // GEMV1 accumulator
__device__ float g_acc2[ACTIONS];              // GEMV2 accumulator

// ---------------- helpers ----------------
__device__ __forceinline__ float warp_sum(float v) {
    #pragma unroll
    for (int o = 16; o > 0; o >>= 1) v += __shfl_xor_sync(0xffffffffu, v, o);
    return v;
}
__device__ __forceinline__ float warp_max(float v) {
    #pragma unroll
    for (int o = 16; o > 0; o >>= 1) v = fmaxf(v, __shfl_xor_sync(0xffffffffu, v, o));
    return v;
}

// ---------------- kernel A: graph aggregation in input dim + zero scratch ----
// Edge buffer dtype is detected at runtime (int32 vs int64): for int64 values
// < 81 stored little-endian, every odd 32-bit word is zero. For genuine int32
// data in [0,81), 64 sampled words across both halves being all-zero has
// probability ~(1/81)^64 ~ 0.
__global__ void kA(const float* __restrict__ x, const int* __restrict__ eraw) {
    __shared__ float degs[N_NODES];
    __shared__ float dinv[N_NODES];
    __shared__ float xcs[N_NODES * IN_DIM];
    __shared__ int is64s;
    const int t = threadIdx.x;

    // zero global accumulators (graph replays need this every launch)
    for (int i = t; i < HIDDEN; i += 1024) g_acc1[i] = 0.f;
    if (t < ACTIONS) g_acc2[t] = 0.f;

    if (t == 0) {
        int any_odd_nonzero = 0;
        #pragma unroll 1
        for (int i = 0; i < 32; i++) {
            any_odd_nonzero |= eraw[2 * i + 1];                   // src half
            any_odd_nonzero |= eraw[2 * (N_EDGES + i) + 1];       // dst half
        }
        is64s = (any_odd_nonzero == 0) ? 1 : 0;
    }
    if (t < N_NODES) degs[t] = 1.f;                 // self loop
    for (int i = t; i < N_NODES * IN_DIM; i += 1024) xcs[i] = 0.f;
    __syncthreads();
    const int is64 = is64s;

    // index accessors (clamped for safety)
    #define SRC(e) min(N_NODES - 1, max(0, is64 ? eraw[2 * (e)] : eraw[(e)]))
    #define DST(e) min(N_NODES - 1, max(0, is64 ? eraw[2 * (N_EDGES + (e))] : eraw[N_EDGES + (e)]))

    for (int e = t; e < N_EDGES; e += 1024)
        atomicAdd(&degs[DST(e)], 1.f);
    __syncthreads();

    if (t < N_NODES) dinv[t] = rsqrtf(degs[t]);
    __syncthreads();

    for (int e = t; e < N_EDGES; e += 1024) {
        int s = SRC(e), d = DST(e);
        float nm = dinv[s] * dinv[d];
        #pragma unroll
        for (int k = 0; k < IN_DIM; k++)
            atomicAdd(&xcs[d * IN_DIM + k], nm * x[s * IN_DIM + k]);
    }
    if (t < N_NODES) {
        float nm = dinv[t] * dinv[t];
        #pragma unroll
        for (int k = 0; k < IN_DIM; k++)
            atomicAdd(&xcs[t * IN_DIM + k], nm * x[t * IN_DIM + k]);
    }
    __syncthreads();
    for (int i = t; i < N_NODES * IN_DIM; i += 1024) g_xc[i] = xcs[i];
    #undef SRC
    #undef DST
}

// ---------------- kernel B: per-node dense row + relu + layernorm ----------
__global__ void __launch_bounds__(256) kB(const float* __restrict__ Wg,
                                          const float* __restrict__ bg) {
    const int n = blockIdx.x;
    const int t = threadIdx.x;
    __shared__ float xcs[IN_DIM];
    __shared__ float hbuf[HIDDEN];            // 32 KB
    __shared__ float s1[8], s2[8], stat[2];

    if (t < IN_DIM) xcs[t] = g_xc[n * IN_DIM + t];
    __syncthreads();

    float c0 = xcs[0], c1 = xcs[1], c2 = xcs[2], c3 = xcs[3], c4 = xcs[4];
    float c5 = xcs[5], c6 = xcs[6], c7 = xcs[7], c8 = xcs[8], c9 = xcs[9];

    float sum = 0.f, sumsq = 0.f;
    for (int j = t; j < HIDDEN; j += 256) {
        float h = bg[j];
        h = fmaf(c0, Wg[0 * HIDDEN + j], h);
        h = fmaf(c1, Wg[1 * HIDDEN + j], h);
        h = fmaf(c2, Wg[2 * HIDDEN + j], h);
        h = fmaf(c3, Wg[3 * HIDDEN + j], h);
        h = fmaf(c4, Wg[4 * HIDDEN + j], h);
        h = fmaf(c5, Wg[5 * HIDDEN + j], h);
        h = fmaf(c6, Wg[6 * HIDDEN + j], h);
        h = fmaf(c7, Wg[7 * HIDDEN + j], h);
        h = fmaf(c8, Wg[8 * HIDDEN + j], h);
        h = fmaf(c9, Wg[9 * HIDDEN + j], h);
        h = fmaxf(h, 0.f);
        hbuf[j] = h;
        sum += h;
        sumsq = fmaf(h, h, sumsq);
    }
    sum = warp_sum(sum);
    sumsq = warp_sum(sumsq);
    const int w = t >> 5, l = t & 31;
    if (l == 0) { s1[w] = sum; s2[w] = sumsq; }
    __syncthreads();
    if (t == 0) {
        float a = 0.f, b = 0.f;
        #pragma unroll
        for (int i = 0; i < 8; i++) { a += s1[i]; b += s2[i]; }
        float mu = a * (1.f / HIDDEN);
        float var = b * (1.f / HIDDEN) - mu * mu;
        stat[0] = mu;
        stat[1] = rsqrtf(var + 1e-5f);
    }
    __syncthreads();
    const float mu = stat[0], rs = stat[1];
    for (int j = t; j < HIDDEN; j += 256)
        g_snorm[n * HIDDEN + j] = (hbuf[j] - mu) * rs;
}

// ---------------- kernel C: pool over nodes + LN affine ----------
__global__ void __launch_bounds__(256) kC(const float* __restrict__ ln_g,
                                          const float* __restrict__ ln_b) {
    const int j = blockIdx.x * 256 + threadIdx.x;
    float s = 0.f;
    #pragma unroll 9
    for (int n = 0; n < N_NODES; n++) s += g_snorm[n * HIDDEN + j];
    g_gvec[j] = fmaf(ln_g[j], s, (float)N_NODES * ln_b[j]);
}

// ---------------- kernel D: split-K GEMV vs W1 (256 MB stream) ----------
#define KC1 128
__global__ void __launch_bounds__(256) kD(const float* __restrict__ W1) {
    const int jc = blockIdx.x;    // 0..7  -> 1024-col chunk
    const int kc = blockIdx.y;    // 0..63 -> 128-row chunk
    const int t = threadIdx.x;
    __shared__ float gs[KC1];
    for (int i = t; i < KC1; i += 256) gs[i] = g_gvec[kc * KC1 + i];
    __syncthreads();

    const int col = jc * 1024 + t * 4;
    const float4* Wp = reinterpret_cast<const float4*>(W1 + (size_t)(kc * KC1) * HIDDEN + col);
    float4 acc = make_float4(0.f, 0.f, 0.f, 0.f);
    #pragma unroll 8
    for (int k = 0; k < KC1; k++) {
        float4 w = Wp[(size_t)k * (HIDDEN / 4)];
        float gv = gs[k];
        acc.x = fmaf(gv, w.x, acc.x);
        acc.y = fmaf(gv, w.y, acc.y);
        acc.z = fmaf(gv, w.z, acc.z);
        acc.w = fmaf(gv, w.w, acc.w);
    }
    atomicAdd(&g_acc1[col + 0], acc.x);
    atomicAdd(&g_acc1[col + 1], acc.y);
    atomicAdd(&g_acc1[col + 2], acc.z);
    atomicAdd(&g_acc1[col + 3], acc.w);
}

// ---------------- kernel E: split-K GEMV vs W2, fused relu(acc1+b1) ------
#define KC2 64
__global__ void __launch_bounds__(256) kE(const float* __restrict__ W2,
                                          const float* __restrict__ b1) {
    const int kc = blockIdx.x;    // 0..127
    const int t = threadIdx.x;
    __shared__ float ys[KC2];
    for (int i = t; i < KC2; i += 256) {
        int k = kc * KC2 + i;
        ys[i] = fmaxf(g_acc1[k] + b1[k], 0.f);
    }
    __syncthreads();
    for (int c = t; c < ACTIONS; c += 256) {
        float a = 0.f;
        #pragma unroll 8
        for (int k = 0; k < KC2; k++)
            a = fmaf(ys[k], W2[(size_t)(kc * KC2 + k) * ACTIONS + c], a);
        atomicAdd(&g_acc2[c], a);
    }
}

// ---------------- kernel F: log_softmax ----------
__global__ void __launch_bounds__(1024) kF(const float* __restrict__ b2,
                                           float* __restrict__ out) {
    const int t = threadIdx.x;
    __shared__ float sm[32];
    __shared__ float bm, bs;

    float v = (t < ACTIONS) ? (g_acc2[t] + b2[t]) : -3.4e38f;

    float m = warp_max(v);
    if ((t & 31) == 0) sm[t >> 5] = m;
    __syncthreads();
    if (t < 32) {
        float mm = sm[t];
        mm = warp_max(mm);
        if (t == 0) bm = mm;
    }
    __syncthreads();
    const float mx = bm;

    float e = (t < ACTIONS) ? expf(v - mx) : 0.f;
    float s = warp_sum(e);
    if ((t & 31) == 0) sm[t >> 5] = s;
    __syncthreads();
    if (t < 32) {
        float ss = sm[t];
        ss = warp_sum(ss);
        if (t == 0) bs = ss;
    }
    __syncthreads();

    if (t < ACTIONS) out[t] = v - mx - logf(bs);
}

// ---------------- launch ----------------
extern "C" void kernel_launch(void* const* d_in, const int* in_sizes, int n_in,
                              void* d_out, int out_size) {
    const float* x    = (const float*)d_in[0];
    const int*   ei   = (const int*)d_in[1];
    const float* Wg   = (const float*)d_in[2];
    const float* bg   = (const float*)d_in[3];
    const float* ln_g = (const float*)d_in[4];
    const float* ln_b = (const float*)d_in[5];
    const float* W1   = (const float*)d_in[6];
    const float* b1   = (const float*)d_in[7];
    const float* W2   = (const float*)d_in[8];
    const float* b2   = (const float*)d_in[9];
    float* out = (float*)d_out;

    kA<<<1, 1024>>>(x, ei);
    kB<<<N_NODES, 256>>>(Wg, bg);
    kC<<<HIDDEN / 256, 256>>>(ln_g, ln_b);
    kD<<<dim3(8, 64), 256>>>(W1);
    kE<<<HIDDEN / KC2, 256>>>(W2, b1);
    kF<<<1, 1024>>>(b2, out);
}

// round 4
// speedup vs baseline: 1.1852x; 1.1852x over previous
#include <cuda_runtime.h>
#include <math.h>

#define N_NODES 81
#define N_EDGES 1620
#define IN_DIM  10
#define HIDDEN  8192
#define ACTIONS 729

// ---------------- device scratch ----------------
__device__ float g_gvec[HIDDEN];   // pooled raw LN sum (pre-affine)
__device__ float g_acc1[HIDDEN];   // GEMV1 accumulator
__device__ float g_acc2[ACTIONS];  // GEMV2 accumulator

__device__ __forceinline__ float warp_sum(float v) {
    #pragma unroll
    for (int o = 16; o > 0; o >>= 1) v += __shfl_xor_sync(0xffffffffu, v, o);
    return v;
}
__device__ __forceinline__ float warp_max(float v) {
    #pragma unroll
    for (int o = 16; o > 0; o >>= 1) v = fmaxf(v, __shfl_xor_sync(0xffffffffu, v, o));
    return v;
}

// ---------------- kZ: zero accumulators (replay-safe) ----------------
#define ZTOT (HIDDEN + HIDDEN + ACTIONS)
__global__ void kZ() {
    int i = blockIdx.x * 1024 + threadIdx.x;
    if (i < HIDDEN) g_gvec[i] = 0.f;
    else if (i < 2 * HIDDEN) g_acc1[i - HIDDEN] = 0.f;
    else if (i < ZTOT) g_acc2[i - 2 * HIDDEN] = 0.f;
}

// ---------------- kB: self-contained per-node GCN row + relu + LN + pool ----
// Each block handles one node: recomputes degrees + its own xc from the edge
// list (L2-resident), keeps its hidden row in registers, reduces LN stats,
// then atomically accumulates the normalized row into g_gvec.
__global__ void __launch_bounds__(256) kB(const float* __restrict__ x,
                                          const int*   __restrict__ eraw,
                                          const float* __restrict__ Wg,
                                          const float* __restrict__ bg) {
    const int n = blockIdx.x;
    const int t = threadIdx.x;
    __shared__ float degs[N_NODES];
    __shared__ float dinv[N_NODES];
    __shared__ float xcs[IN_DIM];
    __shared__ int is64s;
    __shared__ float s1[8], s2[8], stat[2];

    if (t == 0) {
        int any_odd = 0;
        #pragma unroll 1
        for (int i = 0; i < 32; i++) {
            any_odd |= eraw[2 * i + 1];
            any_odd |= eraw[2 * (N_EDGES + i) + 1];
        }
        is64s = (any_odd == 0) ? 1 : 0;
    }
    if (t < N_NODES) degs[t] = 1.f;  // self loop
    if (t < IN_DIM) xcs[t] = 0.f;
    __syncthreads();
    const int is64 = is64s;

    #define SRC(e) min(N_NODES - 1, max(0, is64 ? eraw[2 * (e)] : eraw[(e)]))
    #define DST(e) min(N_NODES - 1, max(0, is64 ? eraw[2 * (N_EDGES + (e))] : eraw[N_EDGES + (e)]))

    for (int e = t; e < N_EDGES; e += 256)
        atomicAdd(&degs[DST(e)], 1.f);
    __syncthreads();
    if (t < N_NODES) dinv[t] = rsqrtf(degs[t]);
    __syncthreads();

    // edges targeting this node only (~20 expected)
    for (int e = t; e < N_EDGES; e += 256) {
        int d = DST(e);
        if (d == n) {
            int s = SRC(e);
            float nm = dinv[s] * dinv[n];
            #pragma unroll
            for (int k = 0; k < IN_DIM; k++)
                atomicAdd(&xcs[k], nm * x[s * IN_DIM + k]);
        }
    }
    // self loop
    if (t == 0) {
        float nm = dinv[n] * dinv[n];
        #pragma unroll
        for (int k = 0; k < IN_DIM; k++)
            atomicAdd(&xcs[k], nm * x[n * IN_DIM + k]);
    }
    __syncthreads();
    #undef SRC
    #undef DST

    const float c0 = xcs[0], c1 = xcs[1], c2 = xcs[2], c3 = xcs[3], c4 = xcs[4];
    const float c5 = xcs[5], c6 = xcs[6], c7 = xcs[7], c8 = xcs[8], c9 = xcs[9];

    float h[HIDDEN / 256];   // 32 floats in registers
    float sum = 0.f, sumsq = 0.f;
    #pragma unroll
    for (int i = 0; i < HIDDEN / 256; i++) {
        const int j = t + i * 256;
        float v = bg[j];
        v = fmaf(c0, Wg[0 * HIDDEN + j], v);
        v = fmaf(c1, Wg[1 * HIDDEN + j], v);
        v = fmaf(c2, Wg[2 * HIDDEN + j], v);
        v = fmaf(c3, Wg[3 * HIDDEN + j], v);
        v = fmaf(c4, Wg[4 * HIDDEN + j], v);
        v = fmaf(c5, Wg[5 * HIDDEN + j], v);
        v = fmaf(c6, Wg[6 * HIDDEN + j], v);
        v = fmaf(c7, Wg[7 * HIDDEN + j], v);
        v = fmaf(c8, Wg[8 * HIDDEN + j], v);
        v = fmaf(c9, Wg[9 * HIDDEN + j], v);
        v = fmaxf(v, 0.f);
        h[i] = v;
        sum += v;
        sumsq = fmaf(v, v, sumsq);
    }
    sum = warp_sum(sum);
    sumsq = warp_sum(sumsq);
    const int w = t >> 5, l = t & 31;
    if (l == 0) { s1[w] = sum; s2[w] = sumsq; }
    __syncthreads();
    if (t == 0) {
        float a = 0.f, b = 0.f;
        #pragma unroll
        for (int i = 0; i < 8; i++) { a += s1[i]; b += s2[i]; }
        float mu = a * (1.f / HIDDEN);
        float var = b * (1.f / HIDDEN) - mu * mu;
        stat[0] = mu;
        stat[1] = rsqrtf(var + 1e-5f);
    }
    __syncthreads();
    const float mu = stat[0], rs = stat[1];
    #pragma unroll
    for (int i = 0; i < HIDDEN / 256; i++)
        atomicAdd(&g_gvec[t + i * 256], (h[i] - mu) * rs);
}

// ---------------- kD: split-K GEMV vs W1, LN affine fused into gs load ------
#define KC1 64
__global__ void __launch_bounds__(256) kD(const float* __restrict__ W1,
                                          const float* __restrict__ ln_g,
                                          const float* __restrict__ ln_b) {
    const int jc = blockIdx.x;    // 0..7   -> 1024-col chunk
    const int kc = blockIdx.y;    // 0..127 -> 64-row chunk
    const int t = threadIdx.x;
    __shared__ float gs[KC1];
    if (t < KC1) {
        const int k = kc * KC1 + t;
        gs[t] = fmaf(ln_g[k], g_gvec[k], (float)N_NODES * ln_b[k]);
    }
    __syncthreads();

    const int col = jc * 1024 + t * 4;
    const float4* Wp = reinterpret_cast<const float4*>(W1 + (size_t)(kc * KC1) * HIDDEN + col);
    float4 acc = make_float4(0.f, 0.f, 0.f, 0.f);
    #pragma unroll 8
    for (int k = 0; k < KC1; k++) {
        float4 wv = Wp[(size_t)k * (HIDDEN / 4)];
        float gv = gs[k];
        acc.x = fmaf(gv, wv.x, acc.x);
        acc.y = fmaf(gv, wv.y, acc.y);
        acc.z = fmaf(gv, wv.z, acc.z);
        acc.w = fmaf(gv, wv.w, acc.w);
    }
    atomicAdd(&g_acc1[col + 0], acc.x);
    atomicAdd(&g_acc1[col + 1], acc.y);
    atomicAdd(&g_acc1[col + 2], acc.z);
    atomicAdd(&g_acc1[col + 3], acc.w);
}

// ---------------- kE: split-K GEMV vs W2, fused relu(acc1+b1) ------
#define KC2 32
__global__ void __launch_bounds__(256) kE(const float* __restrict__ W2,
                                          const float* __restrict__ b1) {
    const int kc = blockIdx.x;    // 0..255
    const int t = threadIdx.x;
    __shared__ float ys[KC2];
    if (t < KC2) {
        const int k = kc * KC2 + t;
        ys[t] = fmaxf(g_acc1[k] + b1[k], 0.f);
    }
    __syncthreads();
    for (int c = t; c < ACTIONS; c += 256) {
        float a = 0.f;
        #pragma unroll 8
        for (int k = 0; k < KC2; k++)
            a = fmaf(ys[k], W2[(size_t)(kc * KC2 + k) * ACTIONS + c], a);
        atomicAdd(&g_acc2[c], a);
    }
}

// ---------------- kF: log_softmax ----------
__global__ void __launch_bounds__(1024) kF(const float* __restrict__ b2,
                                           float* __restrict__ out) {
    const int t = threadIdx.x;
    __shared__ float sm[32];
    __shared__ float bm, bs;

    float v = (t < ACTIONS) ? (g_acc2[t] + b2[t]) : -3.4e38f;

    float m = warp_max(v);
    if ((t & 31) == 0) sm[t >> 5] = m;
    __syncthreads();
    if (t < 32) {
        float mm = sm[t];
        mm = warp_max(mm);
        if (t == 0) bm = mm;
    }
    __syncthreads();
    const float mx = bm;

    float e = (t < ACTIONS) ? expf(v - mx) : 0.f;
    float s = warp_sum(e);
    if ((t & 31) == 0) sm[t >> 5] = s;
    __syncthreads();
    if (t < 32) {
        float ss = sm[t];
        ss = warp_sum(ss);
        if (t == 0) bs = ss;
    }
    __syncthreads();

    if (t < ACTIONS) out[t] = v - mx - logf(bs);
}

// ---------------- launch ----------------
extern "C" void kernel_launch(void* const* d_in, const int* in_sizes, int n_in,
                              void* d_out, int out_size) {
    const float* x    = (const float*)d_in[0];
    const int*   ei   = (const int*)d_in[1];
    const float* Wg   = (const float*)d_in[2];
    const float* bg   = (const float*)d_in[3];
    const float* ln_g = (const float*)d_in[4];
    const float* ln_b = (const float*)d_in[5];
    const float* W1   = (const float*)d_in[6];
    const float* b1   = (const float*)d_in[7];
    const float* W2   = (const float*)d_in[8];
    const float* b2   = (const float*)d_in[9];
    float* out = (float*)d_out;

    kZ<<<(ZTOT + 1023) / 1024, 1024>>>();
    kB<<<N_NODES, 256>>>(x, ei, Wg, bg);
    kD<<<dim3(8, 128), 256>>>(W1, ln_g, ln_b);
    kE<<<HIDDEN / KC2, 256>>>(W2, b1);
    kF<<<1, 1024>>>(b2, out);
}

// round 5
// speedup vs baseline: 1.3457x; 1.1354x over previous
#include <cuda_runtime.h>
#include <math.h>

#define N_NODES 81
#define N_EDGES 1620
#define IN_DIM  10
#define HIDDEN  8192
#define ACTIONS 729

// ---------------- device scratch ----------------
__device__ float g_gvec[HIDDEN];   // pooled raw LN sum (pre-affine)
__device__ float g_acc1[HIDDEN];   // GEMV1 accumulator
__device__ float g_acc2[ACTIONS];  // GEMV2 accumulator
__device__ unsigned int g_cnt;     // kE completion counter

__device__ __forceinline__ float warp_sum(float v) {
    #pragma unroll
    for (int o = 16; o > 0; o >>= 1) v += __shfl_xor_sync(0xffffffffu, v, o);
    return v;
}
__device__ __forceinline__ float warp_max(float v) {
    #pragma unroll
    for (int o = 16; o > 0; o >>= 1) v = fmaxf(v, __shfl_xor_sync(0xffffffffu, v, o));
    return v;
}

// ---------------- kZ: zero accumulators (replay-safe) ----------------
#define ZTOT (HIDDEN + HIDDEN + ACTIONS + 1)
__global__ void kZ() {
    int i = blockIdx.x * 1024 + threadIdx.x;
    if (i < HIDDEN) g_gvec[i] = 0.f;
    else if (i < 2 * HIDDEN) g_acc1[i - HIDDEN] = 0.f;
    else if (i < 2 * HIDDEN + ACTIONS) g_acc2[i - 2 * HIDDEN] = 0.f;
    else if (i == 2 * HIDDEN + ACTIONS) g_cnt = 0u;
}

// ---------------- kB: per-node GCN row + relu + LN + pool (512 thr) ----
__global__ void __launch_bounds__(512) kB(const float* __restrict__ x,
                                          const int*   __restrict__ eraw,
                                          const float* __restrict__ Wg,
                                          const float* __restrict__ bg) {
    const int n = blockIdx.x;
    const int t = threadIdx.x;
    __shared__ float degs[N_NODES];
    __shared__ float dinv[N_NODES];
    __shared__ float xcs[IN_DIM];
    __shared__ int is64s;
    __shared__ float s1[16], s2[16], stat[2];

    if (t == 0) {
        int any_odd = 0;
        #pragma unroll 1
        for (int i = 0; i < 32; i++) {
            any_odd |= eraw[2 * i + 1];
            any_odd |= eraw[2 * (N_EDGES + i) + 1];
        }
        is64s = (any_odd == 0) ? 1 : 0;
    }
    if (t < N_NODES) degs[t] = 1.f;  // self loop
    if (t < IN_DIM) xcs[t] = 0.f;
    __syncthreads();
    const int is64 = is64s;

    #define SRC(e) min(N_NODES - 1, max(0, is64 ? eraw[2 * (e)] : eraw[(e)]))
    #define DST(e) min(N_NODES - 1, max(0, is64 ? eraw[2 * (N_EDGES + (e))] : eraw[N_EDGES + (e)]))

    for (int e = t; e < N_EDGES; e += 512)
        atomicAdd(&degs[DST(e)], 1.f);
    __syncthreads();
    if (t < N_NODES) dinv[t] = rsqrtf(degs[t]);
    __syncthreads();

    for (int e = t; e < N_EDGES; e += 512) {
        int d = DST(e);
        if (d == n) {
            int s = SRC(e);
            float nm = dinv[s] * dinv[n];
            #pragma unroll
            for (int k = 0; k < IN_DIM; k++)
                atomicAdd(&xcs[k], nm * x[s * IN_DIM + k]);
        }
    }
    if (t == 0) {
        float nm = dinv[n] * dinv[n];
        #pragma unroll
        for (int k = 0; k < IN_DIM; k++)
            atomicAdd(&xcs[k], nm * x[n * IN_DIM + k]);
    }
    __syncthreads();
    #undef SRC
    #undef DST

    const float c0 = xcs[0], c1 = xcs[1], c2 = xcs[2], c3 = xcs[3], c4 = xcs[4];
    const float c5 = xcs[5], c6 = xcs[6], c7 = xcs[7], c8 = xcs[8], c9 = xcs[9];

    float h[HIDDEN / 512];   // 16 floats in registers
    float sum = 0.f, sumsq = 0.f;
    #pragma unroll
    for (int i = 0; i < HIDDEN / 512; i++) {
        const int j = t + i * 512;
        float v = bg[j];
        v = fmaf(c0, Wg[0 * HIDDEN + j], v);
        v = fmaf(c1, Wg[1 * HIDDEN + j], v);
        v = fmaf(c2, Wg[2 * HIDDEN + j], v);
        v = fmaf(c3, Wg[3 * HIDDEN + j], v);
        v = fmaf(c4, Wg[4 * HIDDEN + j], v);
        v = fmaf(c5, Wg[5 * HIDDEN + j], v);
        v = fmaf(c6, Wg[6 * HIDDEN + j], v);
        v = fmaf(c7, Wg[7 * HIDDEN + j], v);
        v = fmaf(c8, Wg[8 * HIDDEN + j], v);
        v = fmaf(c9, Wg[9 * HIDDEN + j], v);
        v = fmaxf(v, 0.f);
        h[i] = v;
        sum += v;
        sumsq = fmaf(v, v, sumsq);
    }
    sum = warp_sum(sum);
    sumsq = warp_sum(sumsq);
    const int w = t >> 5, l = t & 31;
    if (l == 0) { s1[w] = sum; s2[w] = sumsq; }
    __syncthreads();
    if (t == 0) {
        float a = 0.f, b = 0.f;
        #pragma unroll
        for (int i = 0; i < 16; i++) { a += s1[i]; b += s2[i]; }
        float mu = a * (1.f / HIDDEN);
        float var = b * (1.f / HIDDEN) - mu * mu;
        stat[0] = mu;
        stat[1] = rsqrtf(var + 1e-5f);
    }
    __syncthreads();
    const float mu = stat[0], rs = stat[1];
    #pragma unroll
    for (int i = 0; i < HIDDEN / 512; i++)
        atomicAdd(&g_gvec[t + i * 512], (h[i] - mu) * rs);
}

// ---------------- kD: split-K GEMV vs W1, LN affine fused into gs load ------
#define KC1 64
__global__ void __launch_bounds__(256) kD(const float* __restrict__ W1,
                                          const float* __restrict__ ln_g,
                                          const float* __restrict__ ln_b) {
    const int jc = blockIdx.x;    // 0..7   -> 1024-col chunk
    const int kc = blockIdx.y;    // 0..127 -> 64-row chunk
    const int t = threadIdx.x;
    __shared__ float gs[KC1];
    if (t < KC1) {
        const int k = kc * KC1 + t;
        gs[t] = fmaf(ln_g[k], g_gvec[k], (float)N_NODES * ln_b[k]);
    }
    __syncthreads();

    const int col = jc * 1024 + t * 4;
    const float4* Wp = reinterpret_cast<const float4*>(W1 + (size_t)(kc * KC1) * HIDDEN + col);
    float4 acc = make_float4(0.f, 0.f, 0.f, 0.f);
    #pragma unroll 8
    for (int k = 0; k < KC1; k++) {
        float4 wv = Wp[(size_t)k * (HIDDEN / 4)];
        float gv = gs[k];
        acc.x = fmaf(gv, wv.x, acc.x);
        acc.y = fmaf(gv, wv.y, acc.y);
        acc.z = fmaf(gv, wv.z, acc.z);
        acc.w = fmaf(gv, wv.w, acc.w);
    }
    atomicAdd(&g_acc1[col + 0], acc.x);
    atomicAdd(&g_acc1[col + 1], acc.y);
    atomicAdd(&g_acc1[col + 2], acc.z);
    atomicAdd(&g_acc1[col + 3], acc.w);
}

// ---------------- kE: split-K/split-N GEMV vs W2 + fused log_softmax -------
#define KC2 32
#define CCH 243                       // 729 / 3 columns per block
#define KE_BLOCKS ((HIDDEN / KC2) * 3)
__global__ void __launch_bounds__(256) kE(const float* __restrict__ W2,
                                          const float* __restrict__ b1,
                                          const float* __restrict__ b2,
                                          float* __restrict__ out) {
    const int kc = blockIdx.x;    // 0..255 -> 32-row chunk
    const int cc = blockIdx.y;    // 0..2   -> 243-col chunk
    const int t = threadIdx.x;
    __shared__ float ys[KC2];
    __shared__ float sm[8];
    __shared__ float bshared;
    __shared__ int lasts;

    if (t < KC2) {
        const int k = kc * KC2 + t;
        ys[t] = fmaxf(g_acc1[k] + b1[k], 0.f);
    }
    __syncthreads();

    const int c = cc * CCH + t;
    if (t < CCH) {
        float a = 0.f;
        const float* Wp = W2 + (size_t)(kc * KC2) * ACTIONS + c;
        #pragma unroll 8
        for (int k = 0; k < KC2; k++)
            a = fmaf(ys[k], Wp[(size_t)k * ACTIONS], a);
        atomicAdd(&g_acc2[c], a);
    }

    // completion counter: last block computes log_softmax
    __threadfence();
    __syncthreads();
    if (t == 0) lasts = (atomicAdd(&g_cnt, 1u) == KE_BLOCKS - 1) ? 1 : 0;
    __syncthreads();
    if (!lasts) return;
    __threadfence();

    float v0 = (t < ACTIONS)        ? (g_acc2[t]        + b2[t])        : -3.4e38f;
    float v1 = (t + 256 < ACTIONS)  ? (g_acc2[t + 256]  + b2[t + 256])  : -3.4e38f;
    float v2 = (t + 512 < ACTIONS)  ? (g_acc2[t + 512]  + b2[t + 512])  : -3.4e38f;

    float m = fmaxf(v0, fmaxf(v1, v2));
    m = warp_max(m);
    if ((t & 31) == 0) sm[t >> 5] = m;
    __syncthreads();
    if (t < 8) {
        float mm = sm[t];
        #pragma unroll
        for (int o = 4; o > 0; o >>= 1) mm = fmaxf(mm, __shfl_xor_sync(0xffu, mm, o));
        if (t == 0) bshared = mm;
    }
    __syncthreads();
    const float mx = bshared;

    float e = 0.f;
    if (t < ACTIONS)       e += expf(v0 - mx);
    if (t + 256 < ACTIONS) e += expf(v1 - mx);
    if (t + 512 < ACTIONS) e += expf(v2 - mx);
    e = warp_sum(e);
    if ((t & 31) == 0) sm[t >> 5] = e;
    __syncthreads();
    if (t < 8) {
        float ss = sm[t];
        #pragma unroll
        for (int o = 4; o > 0; o >>= 1) ss += __shfl_xor_sync(0xffu, ss, o);
        if (t == 0) bshared = ss;
    }
    __syncthreads();
    const float lg = logf(bshared);

    if (t < ACTIONS)       out[t]       = v0 - mx - lg;
    if (t + 256 < ACTIONS) out[t + 256] = v1 - mx - lg;
    if (t + 512 < ACTIONS) out[t + 512] = v2 - mx - lg;
}

// ---------------- launch ----------------
extern "C" void kernel_launch(void* const* d_in, const int* in_sizes, int n_in,
                              void* d_out, int out_size) {
    const float* x    = (const float*)d_in[0];
    const int*   ei   = (const int*)d_in[1];
    const float* Wg   = (const float*)d_in[2];
    const float* bg   = (const float*)d_in[3];
    const float* ln_g = (const float*)d_in[4];
    const float* ln_b = (const float*)d_in[5];
    const float* W1   = (const float*)d_in[6];
    const float* b1   = (const float*)d_in[7];
    const float* W2   = (const float*)d_in[8];
    const float* b2   = (const float*)d_in[9];
    float* out = (float*)d_out;

    kZ<<<(ZTOT + 1023) / 1024, 1024>>>();
    kB<<<N_NODES, 512>>>(x, ei, Wg, bg);
    kD<<<dim3(8, 128), 256>>>(W1, ln_g, ln_b);
    kE<<<dim3(HIDDEN / KC2, 3), 256>>>(W2, b1, b2, out);
}